// round 6
// baseline (speedup 1.0000x reference)
#include <cuda_runtime.h>
#include <cuda_bf16.h>
#include <math.h>
#include <stdint.h>

// Problem constants
#define Bn    128
#define HIDD  64
#define INDIM 2
#define CX    66
#define NN    1024
#define MROWS (Bn * CX)       // 8448
#define RB    2048            // bytes per digit row: [d0 x1024 | d1 x1024]

// power-of-2 scales (digits exact in bf16/fp32)
#define SX   0.0625f              // 2^-4, X-like tensors (X, P2, P4)
#define SXi  16.0f
#define SP   0.00390625f          // 2^-8, P1/P3
#define SPi  256.0f
#define SA   3.0517578125e-05f    // 2^-15, adjacency
#define SAi  32768.0f

// ---------------- scratch (device globals) ----------------
__device__ int8_t g_X [MROWS * RB];
__device__ int8_t g_P1[MROWS * RB];
__device__ int8_t g_P2[MROWS * RB];
__device__ int8_t g_P3[MROWS * RB];
__device__ int8_t g_P4[MROWS * RB];
__device__ int8_t g_A [2 * NN * RB];                 // A0,A1 digit rows
__device__ float  g_RU[Bn * 2 * HIDD * NN];          // sigmoid gates fp32
__device__ __nv_bfloat16 g_Wru[128 * 1024];          // W_ru bf16 3-seg
__device__ __nv_bfloat16 g_WC [64 * 1024];           // W_C  bf16 3-seg

// ---------------- PTX helpers (base ISA only) ----------------
__device__ __forceinline__ uint32_t smem_u32(const void* p) {
    uint32_t a;
    asm("{ .reg .u64 t; cvta.to.shared.u64 t, %1; cvt.u32.u64 %0, t; }" : "=r"(a) : "l"(p));
    return a;
}
__device__ __forceinline__ void cp16(uint32_t dst, const void* src) {
    asm volatile("cp.async.cg.shared.global [%0], [%1], 16;" :: "r"(dst), "l"(src) : "memory");
}
__device__ __forceinline__ void ldm_x4(uint32_t* r, uint32_t a) {
    asm volatile("ldmatrix.sync.aligned.m8n8.x4.shared.b16 {%0,%1,%2,%3}, [%4];"
                 : "=r"(r[0]), "=r"(r[1]), "=r"(r[2]), "=r"(r[3]) : "r"(a));
}
__device__ __forceinline__ void ldm_x4t(uint32_t* r, uint32_t a) {
    asm volatile("ldmatrix.sync.aligned.m8n8.x4.trans.shared.b16 {%0,%1,%2,%3}, [%4];"
                 : "=r"(r[0]), "=r"(r[1]), "=r"(r[2]), "=r"(r[3]) : "r"(a));
}
__device__ __forceinline__ void mma16816(float* c, const uint32_t* a, const uint32_t* b) {
    asm volatile("mma.sync.aligned.m16n8k16.row.col.f32.bf16.bf16.f32 "
                 "{%0,%1,%2,%3},{%4,%5,%6,%7},{%8,%9},{%0,%1,%2,%3};"
                 : "+f"(c[0]), "+f"(c[1]), "+f"(c[2]), "+f"(c[3])
                 : "r"(a[0]), "r"(a[1]), "r"(a[2]), "r"(a[3]), "r"(b[0]), "r"(b[1]));
}
__device__ __forceinline__ void imma16832(int* c, const uint32_t* a, const uint32_t* b) {
    asm volatile("mma.sync.aligned.m16n8k32.row.col.s32.s8.s8.s32 "
                 "{%0,%1,%2,%3},{%4,%5,%6,%7},{%8,%9},{%0,%1,%2,%3};"
                 : "+r"(c[0]), "+r"(c[1]), "+r"(c[2]), "+r"(c[3])
                 : "r"(a[0]), "r"(a[1]), "r"(a[2]), "r"(a[3]), "r"(b[0]), "r"(b[1]));
}
__device__ __forceinline__ int q7(float x) {
    int i = __float2int_rn(x);
    return max(-127, min(127, i));
}

// ============================================================
// Big GEMM via int8 IMMA, 3 digit-product terms.
// D[m,n] = S_in*S_A*( acc1 + acc2/128 ),
//   acc1 = sum d0*e0 ; acc2 = sum (d0*e1 + d1*e0)   (exact int32)
// CTA tile 128x128, warp tile 32x64 (8 warps: 4m x 2n), k-tile 64,
// 4-stage cp.async pipeline, 1 CTA/SM.
// MODE 0 (P1||P3): grid(16,66); x>>3 selects adjacency+output.
// MODE 1 (P2||P4): grid(8,66,2); z selects input/adj/output;
//                  epilogue does 2*D - X0 (dequant X0 @ SX).
// ============================================================
#define NT 16
#define STG 32768                   // (128+128) rows * 128 B
#define SM_TOT (4 * STG)            // 131072

template<int MODE>
__global__ void __launch_bounds__(256, 1)
gemm_big(const int8_t* __restrict__ Xa, const int8_t* __restrict__ Xb,
         const int8_t* __restrict__ Aall, const int8_t* __restrict__ Xsub,
         int8_t* __restrict__ Oa, int8_t* __restrict__ Ob,
         float Sprod, float Sout, float SoutInv)
{
    extern __shared__ char smem[];
    const uint32_t sb = smem_u32(smem);
    const int tid  = threadIdx.x;
    const int lane = tid & 31;
    const int wid  = tid >> 5;
    const int wm   = wid & 3;          // 4 m-blocks of 32
    const int wn   = wid >> 2;         // 2 n-blocks of 64
    const int bm   = blockIdx.y * 128;

    int sel, bnG;
    if (MODE == 0) { sel = blockIdx.x >> 3; bnG = (blockIdx.x & 7) * 128; }
    else           { sel = blockIdx.z;      bnG = blockIdx.x * 128; }
    const int8_t* Xin = (MODE == 0) ? Xa : (sel ? Xb : Xa);
    int8_t* Out = sel ? Ob : Oa;
    const int Arow0 = sel * 1024 + bnG;

    int acc1[2][8][4], acc2[2][8][4];
#pragma unroll
    for (int tm = 0; tm < 2; tm++)
#pragma unroll
        for (int j = 0; j < 8; j++)
#pragma unroll
            for (int e = 0; e < 4; e++) { acc1[tm][j][e] = 0; acc2[tm][j][e] = 0; }

    auto fill = [&](int t) {
        const int kt = t * 64;
        const uint32_t sa = sb + (t & 3) * STG;
        const uint32_t sB = sa + 16384;
        // X rows: 128 rows x 8 chunks (ch0-3 plane d0, ch4-7 plane d1)
#pragma unroll
        for (int j = 0; j < 4; j++) {
            const int u = tid + j * 256;
            const int row = u >> 3, ch = u & 7;
            cp16(sa + row * 128 + ((ch ^ (row & 7)) << 4),
                 Xin + (size_t)(bm + row) * RB + (ch >> 2) * 1024 + kt + (ch & 3) * 16);
        }
        // A rows: 128 rows x 8 chunks
#pragma unroll
        for (int j = 0; j < 4; j++) {
            const int u = tid + j * 256;
            const int row = u >> 3, ch = u & 7;
            cp16(sB + row * 128 + ((ch ^ (row & 7)) << 4),
                 Aall + (size_t)(Arow0 + row) * RB + (ch >> 2) * 1024 + kt + (ch & 3) * 16);
        }
        asm volatile("cp.async.commit_group;" ::: "memory");
    };

    const int arow_l = (lane & 15);
    const int ach_l  = (lane >> 4);
    const int bgrp   = lane >> 3;
    const int brow_l = (lane & 7) + ((bgrp >> 1) << 3);
    const int bch_l  = (bgrp & 1);

    fill(0); fill(1); fill(2);

    for (int t = 0; t < NT; t++) {
        if (t < NT - 2)       asm volatile("cp.async.wait_group 2;" ::: "memory");
        else if (t == NT - 2) asm volatile("cp.async.wait_group 1;" ::: "memory");
        else                  asm volatile("cp.async.wait_group 0;" ::: "memory");
        __syncthreads();
        if (t + 3 < NT) fill(t + 3);
        else asm volatile("cp.async.commit_group;" ::: "memory");

        const uint32_t sa = sb + (t & 3) * STG;
        const uint32_t sB = sa + 16384;
#pragma unroll
        for (int kc = 0; kc < 2; kc++) {
            // A fragments: [plane][m16 tile]
            uint32_t af[2][2][4];
#pragma unroll
            for (int p = 0; p < 2; p++)
#pragma unroll
                for (int tm = 0; tm < 2; tm++) {
                    const int row = wm * 32 + tm * 16 + arow_l;
                    const int ch  = p * 4 + kc * 2 + ach_l;
                    ldm_x4(af[p][tm], sa + row * 128 + ((ch ^ (row & 7)) << 4));
                }
            // B fragments: [plane][n16 tile]
            uint32_t bf_[2][4][4];
#pragma unroll
            for (int p = 0; p < 2; p++)
#pragma unroll
                for (int tn = 0; tn < 4; tn++) {
                    const int row = wn * 64 + tn * 16 + brow_l;
                    const int ch  = p * 4 + kc * 2 + bch_l;
                    ldm_x4(bf_[p][tn], sB + row * 128 + ((ch ^ (row & 7)) << 4));
                }
#pragma unroll
            for (int tm = 0; tm < 2; tm++)
#pragma unroll
                for (int j = 0; j < 8; j++) {
                    imma16832(acc1[tm][j], af[0][tm], &bf_[0][j >> 1][(j & 1) * 2]);
                    imma16832(acc2[tm][j], af[0][tm], &bf_[1][j >> 1][(j & 1) * 2]);
                    imma16832(acc2[tm][j], af[1][tm], &bf_[0][j >> 1][(j & 1) * 2]);
                }
        }
    }

    // ---- epilogue: dequant, (2*D - X0), requantize to digits ----
    const int g  = lane >> 2;
    const int c2 = (lane & 3) * 2;
#pragma unroll
    for (int tm = 0; tm < 2; tm++) {
#pragma unroll
        for (int j = 0; j < 8; j++) {
            const int col = bnG + wn * 64 + j * 8 + c2;
#pragma unroll
            for (int half = 0; half < 2; half++) {
                const int row = bm + wm * 32 + tm * 16 + g + half * 8;
                const size_t base = (size_t)row * RB + col;
                float v0 = Sprod * ((float)acc1[tm][j][half * 2 + 0]
                          + (float)acc2[tm][j][half * 2 + 0] * 0.0078125f);
                float v1 = Sprod * ((float)acc1[tm][j][half * 2 + 1]
                          + (float)acc2[tm][j][half * 2 + 1] * 0.0078125f);
                if (MODE == 1) {
                    const int8_t* xp = Xsub + base;
                    const float x00 = SX * ((float)xp[0] + (float)xp[1024] * 0.0078125f);
                    const float x01 = SX * ((float)xp[1] + (float)xp[1025] * 0.0078125f);
                    v0 = 2.0f * v0 - x00;
                    v1 = 2.0f * v1 - x01;
                }
                const int d00 = q7(v0 * SoutInv);
                const int d01 = q7(v1 * SoutInv);
                const int d10 = q7((v0 - d00 * Sout) * SoutInv * 128.0f);
                const int d11 = q7((v1 - d01 * Sout) * SoutInv * 128.0f);
                *(unsigned short*)(Out + base) =
                    (unsigned short)((d00 & 0xFF) | ((d01 & 0xFF) << 8));
                *(unsigned short*)(Out + base + 1024) =
                    (unsigned short)((d10 & 0xFF) | ((d11 & 0xFF) << 8));
            }
        }
    }
}

// ============================================================
// Projection via bf16 HMMA (3-seg exact split from digits).
// H seg0: S*d0 (hi), seg1: (S/128)*d1 (lo), seg2: S*d0 (hi).
// W segs: hi, hi, lo (precomputed bf16).
// ============================================================
#define PKT 48
#define PNT 21
#define CSTR 132

template<int OTILE, int MODE>
__global__ void __launch_bounds__(256, 2)
proj_mma(const __nv_bfloat16* __restrict__ Wsp, const float* __restrict__ bias,
         const int8_t* __restrict__ p0, const int8_t* __restrict__ p1,
         const int8_t* __restrict__ p2, const int8_t* __restrict__ p3,
         const int8_t* __restrict__ p4,
         const float* __restrict__ RU, const float* __restrict__ hx,
         float* __restrict__ outp)
{
    constexpr int HS_B = PKT * 256;
    constexpr int WS_B = OTILE * 128;
    constexpr int STGP = HS_B + WS_B;
    constexpr int OW   = OTILE / 2;
    constexpr int NJ   = OW / 8;

    extern __shared__ char smem[];
    const uint32_t sb = smem_u32(smem);
    float* Cs = (float*)smem;

    const int tid  = threadIdx.x;
    const int lane = tid & 31;
    const int wid  = tid >> 5;
    const int wm   = wid & 3;
    const int wn   = wid >> 2;
    const int b    = blockIdx.y;
    const int bn0  = blockIdx.x * 128;

    float acc[2][NJ][4];
#pragma unroll
    for (int t2 = 0; t2 < 2; t2++)
#pragma unroll
        for (int j = 0; j < NJ; j++)
#pragma unroll
            for (int e = 0; e < 4; e++) acc[t2][j][e] = 0.0f;

    auto fill = [&](int t) {
        const int seg  = t / 7;
        const int kt   = (t - seg * 7) * PKT;
        const int plane = (seg == 1) ? 1 : 0;
        const float psc = (seg == 1) ? 0.0078125f : 1.0f;
        const uint32_t hs = sb + (t & 1) * STGP;
        const uint32_t ws = hs + HS_B;
        // H digits -> bf16, 48 rows x 16 chunks of 8 elements
#pragma unroll
        for (int j = 0; j < 3; j++) {
            const int u = tid + j * 256;
            const int r = u >> 4, ch = u & 15;
            const int c = kt + r;
            char* dst = smem + (t & 1) * STGP + r * 256 + ((ch ^ (r & 15)) << 4);
            if (c >= 330) {
                *(uint4*)dst = make_uint4(0, 0, 0, 0);
            } else {
                const int p  = c / 66;
                const int cc = c - p * 66;
                const int8_t* src = p0;
                if (p == 1) src = p1;
                else if (p == 2) src = p2;
                else if (p == 3) src = p3;
                else if (p == 4) src = p4;
                const float scale = ((p & 1) ? SP : SX) * psc;
                union { uint2 u2; int8_t s[8]; } L;
                L.u2 = *(const uint2*)(src + ((size_t)b * CX + cc) * RB
                                       + plane * 1024 + bn0 + ch * 8);
                union { uint4 u4; __nv_bfloat16 h[8]; } O;
#pragma unroll
                for (int e = 0; e < 8; e++)
                    O.h[e] = __float2bfloat16((float)L.s[e] * scale);
                *(uint4*)dst = O.u4;
            }
        }
        // W tile via cp.async (unchanged)
#pragma unroll
        for (int j = 0; j < (OTILE * 6 + 255) / 256; j++) {
            const int u = tid + j * 256;
            if (u < OTILE * 6) {
                const int orow = u / 6, wc = u - orow * 6;
                cp16(ws + orow * 128 + ((wc ^ (orow & 7)) << 4),
                     Wsp + (size_t)orow * 1024 + seg * 336 + kt + wc * 8);
            }
        }
        asm volatile("cp.async.commit_group;" ::: "memory");
    };

    const int krow_l = (lane & 7) + ((lane >> 4) << 3);
    const int m8sel  = (lane >> 3) & 1;
    const int bgrp   = lane >> 3;
    const int brow_l = (lane & 7) + ((bgrp >> 1) << 3);
    const int bch_l  = (bgrp & 1);

    fill(0);
    for (int t = 0; t < PNT; t++) {
        if (t + 1 < PNT) {
            fill(t + 1);
            asm volatile("cp.async.wait_group 1;" ::: "memory");
        } else {
            asm volatile("cp.async.wait_group 0;" ::: "memory");
        }
        __syncthreads();

        const uint32_t hs = sb + (t & 1) * STGP;
        const uint32_t ws = hs + HS_B;
#pragma unroll
        for (int ks = 0; ks < 3; ks++) {
            uint32_t afr[2][4];
#pragma unroll
            for (int t2 = 0; t2 < 2; t2++) {
                const int kr  = ks * 16 + krow_l;
                const int chm = (wm * 4) + (t2 * 2) + m8sel;
                ldm_x4t(afr[t2], hs + kr * 256 + ((chm ^ (kr & 15)) << 4));
            }
            uint32_t bfr[NJ / 2 > 0 ? NJ / 2 : 1][4];
#pragma unroll
            for (int tn = 0; tn < NJ / 2; tn++) {
                const int row = wn * OW + tn * 16 + brow_l;
                const int ch  = 2 * ks + bch_l;
                ldm_x4(bfr[tn], ws + row * 128 + ((ch ^ (row & 7)) << 4));
            }
#pragma unroll
            for (int t2 = 0; t2 < 2; t2++)
#pragma unroll
                for (int j = 0; j < NJ; j++)
                    mma16816(acc[t2][j], afr[t2], &bfr[j >> 1][(j & 1) * 2]);
        }
        __syncthreads();
    }

    __syncthreads();
    const int g  = lane >> 2;
    const int c2 = (lane & 3) * 2;
#pragma unroll
    for (int t2 = 0; t2 < 2; t2++)
#pragma unroll
        for (int j = 0; j < NJ; j++)
#pragma unroll
            for (int e = 0; e < 4; e++) {
                const int n = wm * 32 + t2 * 16 + g + (e >> 1) * 8;
                const int o = wn * OW + j * 8 + c2 + (e & 1);
                Cs[o * CSTR + n] = acc[t2][j][e];
            }
    __syncthreads();

    for (int o = wid; o < OTILE; o += 8) {
        const float bv = bias[o];
        const int n = lane * 4;
        float4 v = *(float4*)&Cs[o * CSTR + n];
        if (MODE == 0) {
            v.x = 1.0f / (1.0f + expf(-(v.x + bv)));
            v.y = 1.0f / (1.0f + expf(-(v.y + bv)));
            v.z = 1.0f / (1.0f + expf(-(v.z + bv)));
            v.w = 1.0f / (1.0f + expf(-(v.w + bv)));
            *(float4*)(outp + ((size_t)b * 128 + o) * NN + bn0 + n) = v;
        } else {
            const float4 u4 = *(const float4*)(RU + ((size_t)b * 128 + 64 + o) * NN + bn0 + n);
            const float4 h4 = *(const float4*)(hx + ((size_t)b * HIDD + o) * NN + bn0 + n);
            float4 r;
            r.x = u4.x * h4.x + (1.0f - u4.x) * tanhf(v.x + bv);
            r.y = u4.y * h4.y + (1.0f - u4.y) * tanhf(v.y + bv);
            r.z = u4.z * h4.z + (1.0f - u4.z) * tanhf(v.z + bv);
            r.w = u4.w * h4.w + (1.0f - u4.w) * tanhf(v.w + bv);
            *(float4*)(outp + ((size_t)b * HIDD + o) * NN + bn0 + n) = r;
        }
    }
}

// ============================================================
// quantize / pack kernels
// ============================================================
__device__ __forceinline__ void quant4(const float* f, float invS, float S,
                                       uint32_t& P0, uint32_t& P1)
{
    P0 = 0; P1 = 0;
#pragma unroll
    for (int e = 0; e < 4; e++) {
        const int d0 = q7(f[e] * invS);
        const int d1 = q7((f[e] - d0 * S) * invS * 128.0f);
        P0 |= (uint32_t)(d0 & 0xFF) << (8 * e);
        P1 |= (uint32_t)(d1 & 0xFF) << (8 * e);
    }
}

__global__ void splitA_kernel(const float* __restrict__ A0, const float* __restrict__ A1,
                              int8_t* __restrict__ Aout)
{
    const int idx = blockIdx.x * blockDim.x + threadIdx.x;   // 2*1024*256
    if (idx >= 2 * NN * 256) return;
    const int adj = idx >> 18;
    const int r   = idx & ((1 << 18) - 1);
    const int row = r >> 8;
    const int n4  = r & 255;
    const float4 v = ((const float4*)(adj ? A1 : A0))[(size_t)row * 256 + n4];
    const float f[4] = { v.x, v.y, v.z, v.w };
    uint32_t P0, P1;
    quant4(f, SAi, SA, P0, P1);
    int8_t* dst = Aout + (size_t)(adj * NN + row) * RB + n4 * 4;
    *(uint32_t*)(dst)        = P0;
    *(uint32_t*)(dst + 1024) = P1;
}

__global__ void splitW_kernel(const float* __restrict__ W_ru, const float* __restrict__ W_C,
                              __nv_bfloat16* __restrict__ Wru, __nv_bfloat16* __restrict__ WC)
{
    const int idx = blockIdx.x * blockDim.x + threadIdx.x;
    if (idx >= 192 * 336) return;
    const int o = idx / 336;
    const int c = idx - o * 336;
    float w = 0.0f;
    if (c < 330) w = (o < 128) ? W_ru[(size_t)o * 330 + c] : W_C[(size_t)(o - 128) * 330 + c];
    const __nv_bfloat16 hi = __float2bfloat16(w);
    const __nv_bfloat16 lo = __float2bfloat16(w - __bfloat162float(hi));
    __nv_bfloat16* dst = (o < 128) ? (Wru + (size_t)o * 1024) : (WC + (size_t)(o - 128) * 1024);
    dst[c]       = hi;
    dst[336 + c] = hi;
    dst[672 + c] = lo;
}

__global__ void pack1_kernel(const float* __restrict__ inputs, const float* __restrict__ hx,
                             int8_t* __restrict__ X)
{
    const int idx = blockIdx.x * blockDim.x + threadIdx.x;
    if (idx >= MROWS * 256) return;
    const int n4 = idx & 255;
    const int t  = idx >> 8;
    const int c  = t % CX;
    const int b  = t / CX;
    float4 v;
    if (c < INDIM)
        v = ((const float4*)inputs)[((size_t)b * INDIM + c) * 256 + n4];
    else
        v = ((const float4*)hx)[((size_t)b * HIDD + (c - INDIM)) * 256 + n4];
    const float f[4] = { v.x, v.y, v.z, v.w };
    uint32_t P0, P1;
    quant4(f, SXi, SX, P0, P1);
    int8_t* dst = X + (size_t)t * RB + n4 * 4;
    *(uint32_t*)(dst)        = P0;
    *(uint32_t*)(dst + 1024) = P1;
}

__global__ void pack2_kernel(const float* __restrict__ inputs, const float* __restrict__ hx,
                             const float* __restrict__ RU, int8_t* __restrict__ X)
{
    const int idx = blockIdx.x * blockDim.x + threadIdx.x;
    if (idx >= MROWS * 256) return;
    const int n4 = idx & 255;
    const int t  = idx >> 8;
    const int c  = t % CX;
    const int b  = t / CX;
    float4 v;
    if (c < INDIM) {
        v = ((const float4*)inputs)[((size_t)b * INDIM + c) * 256 + n4];
    } else {
        const int cc = c - INDIM;
        const float4 r = ((const float4*)RU)[((size_t)b * 128 + cc) * 256 + n4];
        const float4 h = ((const float4*)hx)[((size_t)b * HIDD + cc) * 256 + n4];
        v.x = r.x * h.x; v.y = r.y * h.y; v.z = r.z * h.z; v.w = r.w * h.w;
    }
    const float f[4] = { v.x, v.y, v.z, v.w };
    uint32_t P0, P1;
    quant4(f, SXi, SX, P0, P1);
    int8_t* dst = X + (size_t)t * RB + n4 * 4;
    *(uint32_t*)(dst)        = P0;
    *(uint32_t*)(dst + 1024) = P1;
}

// ============================================================
extern "C" void kernel_launch(void* const* d_in, const int* in_sizes, int n_in,
                              void* d_out, int out_size)
{
    const float* inputs = (const float*)d_in[0];
    const float* hx     = (const float*)d_in[1];
    const float* A0     = (const float*)d_in[2];
    const float* A1     = (const float*)d_in[3];
    const float* W_ru   = (const float*)d_in[4];
    const float* b_ru   = (const float*)d_in[5];
    const float* W_C    = (const float*)d_in[6];
    const float* b_C    = (const float*)d_in[7];
    float* out = (float*)d_out;

    int8_t *gX, *gP1, *gP2, *gP3, *gP4, *gA;
    __nv_bfloat16 *gWru, *gWC;
    float *gRU;
    cudaGetSymbolAddress((void**)&gX,  g_X);
    cudaGetSymbolAddress((void**)&gP1, g_P1);
    cudaGetSymbolAddress((void**)&gP2, g_P2);
    cudaGetSymbolAddress((void**)&gP3, g_P3);
    cudaGetSymbolAddress((void**)&gP4, g_P4);
    cudaGetSymbolAddress((void**)&gA,  g_A);
    cudaGetSymbolAddress((void**)&gRU, g_RU);
    cudaGetSymbolAddress((void**)&gWru, g_Wru);
    cudaGetSymbolAddress((void**)&gWC,  g_WC);

    static bool attr_set = false;
    if (!attr_set) {
        cudaFuncSetAttribute(gemm_big<0>, cudaFuncAttributeMaxDynamicSharedMemorySize, SM_TOT);
        cudaFuncSetAttribute(gemm_big<1>, cudaFuncAttributeMaxDynamicSharedMemorySize, SM_TOT);
        cudaFuncSetAttribute(proj_mma<128, 0>, cudaFuncAttributeMaxDynamicSharedMemorySize, 128 * CSTR * 4);
        cudaFuncSetAttribute(proj_mma<64, 1>,  cudaFuncAttributeMaxDynamicSharedMemorySize, 64 * 1024);
        attr_set = true;
    }
    const int smem0 = 128 * CSTR * 4;
    const int smem1 = 2 * (PKT * 256 + 64 * 128) > 64 * CSTR * 4
                    ? 2 * (PKT * 256 + 64 * 128) : 64 * CSTR * 4;

    const int packBlocks = (MROWS * 256 + 255) / 256;
    const float Sprod0 = SX * SA;   // X @ A
    const float Sprod1 = SP * SA;   // P @ A

    splitA_kernel<<<(2 * NN * 256 + 255) / 256, 256>>>(A0, A1, gA);
    splitW_kernel<<<(192 * 336 + 255) / 256, 256>>>(W_ru, W_C, gWru, gWC);

    // ---------- pass 1: ru gates ----------
    pack1_kernel<<<packBlocks, 256>>>(inputs, hx, gX);
    gemm_big<0><<<dim3(16, MROWS / 128), 256, SM_TOT>>>(gX, nullptr, gA, nullptr,
                                                        gP1, gP3, Sprod0, SP, SPi);
    gemm_big<1><<<dim3(8, MROWS / 128, 2), 256, SM_TOT>>>(gP1, gP3, gA, gX,
                                                          gP2, gP4, Sprod1, SX, SXi);
    proj_mma<128, 0><<<dim3(8, Bn), 256, smem0>>>(gWru, b_ru, gX, gP1, gP2, gP3, gP4,
                                                  nullptr, nullptr, gRU);

    // ---------- pass 2: candidate + output ----------
    pack2_kernel<<<packBlocks, 256>>>(inputs, hx, gRU, gX);
    gemm_big<0><<<dim3(16, MROWS / 128), 256, SM_TOT>>>(gX, nullptr, gA, nullptr,
                                                        gP1, gP3, Sprod0, SP, SPi);
    gemm_big<1><<<dim3(8, MROWS / 128, 2), 256, SM_TOT>>>(gP1, gP3, gA, gX,
                                                          gP2, gP4, Sprod1, SX, SXi);
    proj_mma<64, 1><<<dim3(8, Bn), 256, smem1>>>(gWC, b_C, gX, gP1, gP2, gP3, gP4,
                                                 gRU, hx, out);
}

// round 7
// speedup vs baseline: 3.4395x; 3.4395x over previous
#include <cuda_runtime.h>
#include <cuda_fp16.h>
#include <math.h>
#include <stdint.h>

// Problem constants
#define Bn    128
#define HIDD  64
#define INDIM 2
#define CX    66
#define NN    1024
#define MROWS (Bn * CX)       // 8448
#define KW    2048            // hi|lo fp16 packed width per X-like row

// ---------------- scratch (device globals) ----------------
__device__ __half g_X [MROWS * KW];
__device__ __half g_P1[MROWS * KW];
__device__ __half g_P2[MROWS * KW];
__device__ __half g_P3[MROWS * KW];
__device__ __half g_P4[MROWS * KW];
__device__ __half g_A [2 * NN * NN];                 // A0,A1 single fp16 (2048 rows x 1024)
__device__ float  g_RU[Bn * 2 * HIDD * NN];          // sigmoid gates fp32
__device__ __half g_Wru[128 * 1024];                 // W_ru fp16, 2 identical segs
__device__ __half g_WC [64 * 1024];                  // W_C  fp16, 2 identical segs

// ---------------- PTX helpers (base ISA only) ----------------
__device__ __forceinline__ uint32_t smem_u32(const void* p) {
    uint32_t a;
    asm("{ .reg .u64 t; cvta.to.shared.u64 t, %1; cvt.u32.u64 %0, t; }" : "=r"(a) : "l"(p));
    return a;
}
__device__ __forceinline__ void cp16(uint32_t dst, const void* src) {
    asm volatile("cp.async.cg.shared.global [%0], [%1], 16;" :: "r"(dst), "l"(src) : "memory");
}
__device__ __forceinline__ void ldm_x4(uint32_t* r, uint32_t a) {
    asm volatile("ldmatrix.sync.aligned.m8n8.x4.shared.b16 {%0,%1,%2,%3}, [%4];"
                 : "=r"(r[0]), "=r"(r[1]), "=r"(r[2]), "=r"(r[3]) : "r"(a));
}
__device__ __forceinline__ void ldm_x4t(uint32_t* r, uint32_t a) {
    asm volatile("ldmatrix.sync.aligned.m8n8.x4.trans.shared.b16 {%0,%1,%2,%3}, [%4];"
                 : "=r"(r[0]), "=r"(r[1]), "=r"(r[2]), "=r"(r[3]) : "r"(a));
}
__device__ __forceinline__ void mma16816(float* c, const uint32_t* a, const uint32_t* b) {
    asm volatile("mma.sync.aligned.m16n8k16.row.col.f32.f16.f16.f32 "
                 "{%0,%1,%2,%3},{%4,%5,%6,%7},{%8,%9},{%0,%1,%2,%3};"
                 : "+f"(c[0]), "+f"(c[1]), "+f"(c[2]), "+f"(c[3])
                 : "r"(a[0]), "r"(a[1]), "r"(a[2]), "r"(a[3]), "r"(b[0]), "r"(b[1]));
}

// ============================================================
// Big GEMM via fp16 HMMA, 2 split segments (K=2048 total).
// D[m,n] = Xhi[m,:]*A[n,:] + Xlo[m,:]*A[n,:]
// Out(hi|lo fp16) = split( doBeta ? 2*D - X0 : D )
// CTA tile 128x128, warp tile 32x64 (8 warps), k-tile 64,
// 3-stage cp.async pipeline, 2 CTAs/SM.
// ============================================================
#define MB 128
#define NT 32
#define STG_BYTES 32768            // (128+128)*64*2
#define SM_TOT (3 * STG_BYTES)     // 98304

__global__ void __launch_bounds__(256, 2)
mma_gemm(const __half* __restrict__ Xin,
         const __half* __restrict__ Ain,
         const __half* __restrict__ X0,
         __half* __restrict__ Out,
         int doBeta)
{
    extern __shared__ char smem[];
    const uint32_t sb = smem_u32(smem);
    const int tid  = threadIdx.x;
    const int lane = tid & 31;
    const int wid  = tid >> 5;
    const int wm   = wid & 3;
    const int wn   = wid >> 2;
    const int bm   = blockIdx.y * MB;
    const int bn   = blockIdx.x * MB;

    float acc[2][8][4];
#pragma unroll
    for (int t2 = 0; t2 < 2; t2++)
#pragma unroll
        for (int j = 0; j < 8; j++)
#pragma unroll
            for (int e = 0; e < 4; e++) acc[t2][j][e] = 0.0f;

    auto fill = [&](int t) {
        const int s    = t >> 4;               // segment 0 (hi) / 1 (lo)
        const int kt   = (t & 15) * 64;
        const int xoff = s * 1024;
        const uint32_t sa = sb + (t % 3) * STG_BYTES;
        const uint32_t sB = sa + 16384;
#pragma unroll
        for (int j = 0; j < 4; j++) {
            const int u = tid + j * 256;
            const int row = u >> 3, ch = u & 7;
            cp16(sa + row * 128 + ((ch ^ (row & 7)) << 4),
                 Xin + (size_t)(bm + row) * KW + xoff + kt + ch * 8);
        }
#pragma unroll
        for (int j = 0; j < 4; j++) {
            const int u = tid + j * 256;
            const int row = u >> 3, ch = u & 7;
            cp16(sB + row * 128 + ((ch ^ (row & 7)) << 4),
                 Ain + (size_t)(bn + row) * NN + kt + ch * 8);
        }
        asm volatile("cp.async.commit_group;" ::: "memory");
    };

    const int arow_l = (lane & 15);
    const int ach_l  = (lane >> 4);
    const int bgrp   = lane >> 3;
    const int brow_l = (lane & 7) + ((bgrp >> 1) << 3);
    const int bch_l  = (bgrp & 1);

    fill(0);
    fill(1);

    for (int t = 0; t < NT; t++) {
        if (t < NT - 1) asm volatile("cp.async.wait_group 1;" ::: "memory");
        else            asm volatile("cp.async.wait_group 0;" ::: "memory");
        __syncthreads();
        if (t + 2 < NT) fill(t + 2);

        const uint32_t sa = sb + (t % 3) * STG_BYTES;
        const uint32_t sB = sa + 16384;
#pragma unroll
        for (int ks = 0; ks < 4; ks++) {
            uint32_t afr[2][4];
#pragma unroll
            for (int t2 = 0; t2 < 2; t2++) {
                const int row = wm * 32 + t2 * 16 + arow_l;
                const int ch  = 2 * ks + ach_l;
                ldm_x4(afr[t2], sa + row * 128 + ((ch ^ (row & 7)) << 4));
            }
            uint32_t bfr[4][4];
#pragma unroll
            for (int tn = 0; tn < 4; tn++) {
                const int row = wn * 64 + tn * 16 + brow_l;
                const int ch  = 2 * ks + bch_l;
                ldm_x4(bfr[tn], sB + row * 128 + ((ch ^ (row & 7)) << 4));
            }
#pragma unroll
            for (int t2 = 0; t2 < 2; t2++)
#pragma unroll
                for (int j = 0; j < 8; j++)
                    mma16816(acc[t2][j], afr[t2], &bfr[j >> 1][(j & 1) * 2]);
        }
    }

    // ---- epilogue: (optional 2*D - X0), split to fp16 hi|lo ----
    const int g  = lane >> 2;
    const int c2 = (lane & 3) * 2;
#pragma unroll
    for (int t2 = 0; t2 < 2; t2++) {
#pragma unroll
        for (int j = 0; j < 8; j++) {
            const int col = bn + wn * 64 + j * 8 + c2;
#pragma unroll
            for (int half = 0; half < 2; half++) {
                const int row = bm + wm * 32 + t2 * 16 + g + half * 8;
                const size_t base = (size_t)row * KW + col;
                float v0 = acc[t2][j][half * 2 + 0];
                float v1 = acc[t2][j][half * 2 + 1];
                if (doBeta) {
                    union { uint32_t u; __half h[2]; } Hh, Hl;
                    Hh.u = *(const uint32_t*)(X0 + base);
                    Hl.u = *(const uint32_t*)(X0 + base + 1024);
                    v0 = 2.0f * v0 - (__half2float(Hh.h[0]) + __half2float(Hl.h[0]));
                    v1 = 2.0f * v1 - (__half2float(Hh.h[1]) + __half2float(Hl.h[1]));
                }
                union { uint32_t u; __half h[2]; } Oh, Ol;
                Oh.h[0] = __float2half_rn(v0);
                Oh.h[1] = __float2half_rn(v1);
                Ol.h[0] = __float2half_rn(v0 - __half2float(Oh.h[0]));
                Ol.h[1] = __float2half_rn(v1 - __half2float(Oh.h[1]));
                *(uint32_t*)(Out + base)        = Oh.u;
                *(uint32_t*)(Out + base + 1024) = Ol.u;
            }
        }
    }
}

// ============================================================
// Projection via fp16 HMMA. 2 segments (Hhi*W + Hlo*W), K=672.
// MODE 0: RU = sigmoid(W@H+b). MODE 1: out = u*hx+(1-u)*tanh(W@H+b).
// grid (8, Bn), 256 threads, 8 warps = 4(n) x 2(o).
// ============================================================
#define PKT 48
#define PNT 14
#define CSTR 132

template<int OTILE, int MODE>
__global__ void __launch_bounds__(256, 2)
proj_mma(const __half* __restrict__ Wsp, const float* __restrict__ bias,
         const __half* __restrict__ p0, const __half* __restrict__ p1,
         const __half* __restrict__ p2, const __half* __restrict__ p3,
         const __half* __restrict__ p4,
         const float* __restrict__ RU, const float* __restrict__ hx,
         float* __restrict__ outp)
{
    constexpr int HS_B = PKT * 256;
    constexpr int WS_B = OTILE * 128;
    constexpr int STGP = HS_B + WS_B;
    constexpr int OW   = OTILE / 2;
    constexpr int NJ   = OW / 8;

    extern __shared__ char smem[];
    const uint32_t sb = smem_u32(smem);
    float* Cs = (float*)smem;

    const int tid  = threadIdx.x;
    const int lane = tid & 31;
    const int wid  = tid >> 5;
    const int wm   = wid & 3;
    const int wn   = wid >> 2;
    const int b    = blockIdx.y;
    const int bn0  = blockIdx.x * 128;

    float acc[2][NJ][4];
#pragma unroll
    for (int t2 = 0; t2 < 2; t2++)
#pragma unroll
        for (int j = 0; j < NJ; j++)
#pragma unroll
            for (int e = 0; e < 4; e++) acc[t2][j][e] = 0.0f;

    auto fill = [&](int t) {
        const int seg  = t / 7;                 // 0: hi plane, 1: lo plane
        const int kt   = (t - seg * 7) * PKT;
        const int hoff = seg * 1024;
        const uint32_t hs = sb + (t & 1) * STGP;
        const uint32_t ws = hs + HS_B;
#pragma unroll
        for (int j = 0; j < 3; j++) {
            const int u = tid + j * 256;
            const int r = u >> 4, ch = u & 15;
            int c = kt + r;
            if (c >= 330) c = 0;                // W rows are zero there
            const int p  = c / 66;
            const int cc = c - p * 66;
            const __half* src = p0;
            if (p == 1) src = p1;
            else if (p == 2) src = p2;
            else if (p == 3) src = p3;
            else if (p == 4) src = p4;
            cp16(hs + r * 256 + ((ch ^ (r & 15)) << 4),
                 src + ((size_t)b * CX + cc) * KW + hoff + bn0 + ch * 8);
        }
#pragma unroll
        for (int j = 0; j < (OTILE * 6 + 255) / 256; j++) {
            const int u = tid + j * 256;
            if (u < OTILE * 6) {
                const int orow = u / 6, wc = u - orow * 6;
                cp16(ws + orow * 128 + ((wc ^ (orow & 7)) << 4),
                     Wsp + (size_t)orow * 1024 + seg * 336 + kt + wc * 8);
            }
        }
        asm volatile("cp.async.commit_group;" ::: "memory");
    };

    const int krow_l = (lane & 7) + ((lane >> 4) << 3);
    const int m8sel  = (lane >> 3) & 1;
    const int bgrp   = lane >> 3;
    const int brow_l = (lane & 7) + ((bgrp >> 1) << 3);
    const int bch_l  = (bgrp & 1);

    fill(0);
    for (int t = 0; t < PNT; t++) {
        if (t + 1 < PNT) {
            fill(t + 1);
            asm volatile("cp.async.wait_group 1;" ::: "memory");
        } else {
            asm volatile("cp.async.wait_group 0;" ::: "memory");
        }
        __syncthreads();

        const uint32_t hs = sb + (t & 1) * STGP;
        const uint32_t ws = hs + HS_B;
#pragma unroll
        for (int ks = 0; ks < 3; ks++) {
            uint32_t afr[2][4];
#pragma unroll
            for (int t2 = 0; t2 < 2; t2++) {
                const int kr  = ks * 16 + krow_l;
                const int chm = (wm * 4) + (t2 * 2) + m8sel;
                ldm_x4t(afr[t2], hs + kr * 256 + ((chm ^ (kr & 15)) << 4));
            }
            uint32_t bfr[NJ / 2 > 0 ? NJ / 2 : 1][4];
#pragma unroll
            for (int tn = 0; tn < NJ / 2; tn++) {
                const int row = wn * OW + tn * 16 + brow_l;
                const int ch  = 2 * ks + bch_l;
                ldm_x4(bfr[tn], ws + row * 128 + ((ch ^ (row & 7)) << 4));
            }
#pragma unroll
            for (int t2 = 0; t2 < 2; t2++)
#pragma unroll
                for (int j = 0; j < NJ; j++)
                    mma16816(acc[t2][j], afr[t2], &bfr[j >> 1][(j & 1) * 2]);
        }
        __syncthreads();
    }

    __syncthreads();
    const int g  = lane >> 2;
    const int c2 = (lane & 3) * 2;
#pragma unroll
    for (int t2 = 0; t2 < 2; t2++)
#pragma unroll
        for (int j = 0; j < NJ; j++)
#pragma unroll
            for (int e = 0; e < 4; e++) {
                const int n = wm * 32 + t2 * 16 + g + (e >> 1) * 8;
                const int o = wn * OW + j * 8 + c2 + (e & 1);
                Cs[o * CSTR + n] = acc[t2][j][e];
            }
    __syncthreads();

    for (int o = wid; o < OTILE; o += 8) {
        const float bv = bias[o];
        const int n = lane * 4;
        float4 v = *(float4*)&Cs[o * CSTR + n];
        if (MODE == 0) {
            v.x = 1.0f / (1.0f + expf(-(v.x + bv)));
            v.y = 1.0f / (1.0f + expf(-(v.y + bv)));
            v.z = 1.0f / (1.0f + expf(-(v.z + bv)));
            v.w = 1.0f / (1.0f + expf(-(v.w + bv)));
            *(float4*)(outp + ((size_t)b * 128 + o) * NN + bn0 + n) = v;
        } else {
            const float4 u4 = *(const float4*)(RU + ((size_t)b * 128 + 64 + o) * NN + bn0 + n);
            const float4 h4 = *(const float4*)(hx + ((size_t)b * HIDD + o) * NN + bn0 + n);
            float4 r;
            r.x = u4.x * h4.x + (1.0f - u4.x) * tanhf(v.x + bv);
            r.y = u4.y * h4.y + (1.0f - u4.y) * tanhf(v.y + bv);
            r.z = u4.z * h4.z + (1.0f - u4.z) * tanhf(v.z + bv);
            r.w = u4.w * h4.w + (1.0f - u4.w) * tanhf(v.w + bv);
            *(float4*)(outp + ((size_t)b * HIDD + o) * NN + bn0 + n) = r;
        }
    }
}

// ============================================================
// split / pack kernels (fp32 -> fp16 hi|lo; A/W -> single fp16)
// ============================================================
__device__ __forceinline__ void split4h(const float4 v, __half* hi4, __half* lo4) {
    const float f[4] = { v.x, v.y, v.z, v.w };
#pragma unroll
    for (int e = 0; e < 4; e++) {
        const __half h = __float2half_rn(f[e]);
        hi4[e] = h;
        lo4[e] = __float2half_rn(f[e] - __half2float(h));
    }
}

__global__ void splitA_kernel(const float* __restrict__ A0, const float* __restrict__ A1,
                              __half* __restrict__ Aout)
{
    const int idx = blockIdx.x * blockDim.x + threadIdx.x;   // 2*1024*256
    if (idx >= 2 * NN * 256) return;
    const int adj = idx >> 18;
    const int r   = idx & ((1 << 18) - 1);
    const int row = r >> 8;
    const int n4  = r & 255;
    const float4 v = ((const float4*)(adj ? A1 : A0))[(size_t)row * 256 + n4];
    union { uint2 u; __half h[4]; } H;
    H.h[0] = __float2half_rn(v.x);
    H.h[1] = __float2half_rn(v.y);
    H.h[2] = __float2half_rn(v.z);
    H.h[3] = __float2half_rn(v.w);
    *(uint2*)(Aout + (size_t)(adj * NN + row) * NN + n4 * 4) = H.u;
}

__global__ void splitW_kernel(const float* __restrict__ W_ru, const float* __restrict__ W_C,
                              __half* __restrict__ Wru, __half* __restrict__ WC)
{
    const int idx = blockIdx.x * blockDim.x + threadIdx.x;
    if (idx >= 192 * 336) return;
    const int o = idx / 336;
    const int c = idx - o * 336;
    float w = 0.0f;
    if (c < 330) w = (o < 128) ? W_ru[(size_t)o * 330 + c] : W_C[(size_t)(o - 128) * 330 + c];
    const __half h = __float2half_rn(w);
    __half* dst = (o < 128) ? (Wru + (size_t)o * 1024) : (WC + (size_t)(o - 128) * 1024);
    dst[c]       = h;   // segment 0
    dst[336 + c] = h;   // segment 1 (same W; H planes differ)
}

__global__ void pack1_kernel(const float* __restrict__ inputs, const float* __restrict__ hx,
                             __half* __restrict__ X)
{
    const int idx = blockIdx.x * blockDim.x + threadIdx.x;
    if (idx >= MROWS * 256) return;
    const int n4 = idx & 255;
    const int t  = idx >> 8;
    const int c  = t % CX;
    const int b  = t / CX;
    float4 v;
    if (c < INDIM)
        v = ((const float4*)inputs)[((size_t)b * INDIM + c) * 256 + n4];
    else
        v = ((const float4*)hx)[((size_t)b * HIDD + (c - INDIM)) * 256 + n4];
    union { uint2 u; __half h[4]; } H, L;
    split4h(v, H.h, L.h);
    __half* dst = X + (size_t)t * KW + n4 * 4;
    *(uint2*)(dst)        = H.u;
    *(uint2*)(dst + 1024) = L.u;
}

__global__ void pack2_kernel(const float* __restrict__ inputs, const float* __restrict__ hx,
                             const float* __restrict__ RU, __half* __restrict__ X)
{
    const int idx = blockIdx.x * blockDim.x + threadIdx.x;
    if (idx >= MROWS * 256) return;
    const int n4 = idx & 255;
    const int t  = idx >> 8;
    const int c  = t % CX;
    const int b  = t / CX;
    float4 v;
    if (c < INDIM) {
        v = ((const float4*)inputs)[((size_t)b * INDIM + c) * 256 + n4];
    } else {
        const int cc = c - INDIM;
        const float4 r = ((const float4*)RU)[((size_t)b * 128 + cc) * 256 + n4];
        const float4 h = ((const float4*)hx)[((size_t)b * HIDD + cc) * 256 + n4];
        v.x = r.x * h.x; v.y = r.y * h.y; v.z = r.z * h.z; v.w = r.w * h.w;
    }
    union { uint2 u; __half h[4]; } H, L;
    split4h(v, H.h, L.h);
    __half* dst = X + (size_t)t * KW + n4 * 4;
    *(uint2*)(dst)        = H.u;
    *(uint2*)(dst + 1024) = L.u;
}

// ============================================================
extern "C" void kernel_launch(void* const* d_in, const int* in_sizes, int n_in,
                              void* d_out, int out_size)
{
    const float* inputs = (const float*)d_in[0];
    const float* hx     = (const float*)d_in[1];
    const float* A0     = (const float*)d_in[2];
    const float* A1     = (const float*)d_in[3];
    const float* W_ru   = (const float*)d_in[4];
    const float* b_ru   = (const float*)d_in[5];
    const float* W_C    = (const float*)d_in[6];
    const float* b_C    = (const float*)d_in[7];
    float* out = (float*)d_out;

    __half *gX, *gP1, *gP2, *gP3, *gP4, *gA, *gWru, *gWC;
    float *gRU;
    cudaGetSymbolAddress((void**)&gX,  g_X);
    cudaGetSymbolAddress((void**)&gP1, g_P1);
    cudaGetSymbolAddress((void**)&gP2, g_P2);
    cudaGetSymbolAddress((void**)&gP3, g_P3);
    cudaGetSymbolAddress((void**)&gP4, g_P4);
    cudaGetSymbolAddress((void**)&gA,  g_A);
    cudaGetSymbolAddress((void**)&gRU, g_RU);
    cudaGetSymbolAddress((void**)&gWru, g_Wru);
    cudaGetSymbolAddress((void**)&gWC,  g_WC);

    static bool attr_set = false;
    if (!attr_set) {
        cudaFuncSetAttribute(mma_gemm, cudaFuncAttributeMaxDynamicSharedMemorySize, SM_TOT);
        cudaFuncSetAttribute(proj_mma<128, 0>, cudaFuncAttributeMaxDynamicSharedMemorySize, 128 * CSTR * 4);
        cudaFuncSetAttribute(proj_mma<64, 1>,  cudaFuncAttributeMaxDynamicSharedMemorySize, 64 * 1024);
        attr_set = true;
    }
    const int smem0 = 128 * CSTR * 4;
    const int smem1 = 2 * (PKT * 256 + 64 * 128) > 64 * CSTR * 4
                    ? 2 * (PKT * 256 + 64 * 128) : 64 * CSTR * 4;

    const dim3 ggrid(NN / MB, MROWS / MB);   // (8, 66)
    const int packBlocks = (MROWS * 256 + 255) / 256;
    const __half* gA0 = gA;
    const __half* gA1 = gA + (size_t)NN * NN;

    splitA_kernel<<<(2 * NN * 256 + 255) / 256, 256>>>(A0, A1, gA);
    splitW_kernel<<<(192 * 336 + 255) / 256, 256>>>(W_ru, W_C, gWru, gWC);

    // ---------- pass 1: ru gates ----------
    pack1_kernel<<<packBlocks, 256>>>(inputs, hx, gX);
    mma_gemm<<<ggrid, 256, SM_TOT>>>(gX,  gA0, nullptr, gP1, 0);
    mma_gemm<<<ggrid, 256, SM_TOT>>>(gP1, gA0, gX,      gP2, 1);
    mma_gemm<<<ggrid, 256, SM_TOT>>>(gX,  gA1, nullptr, gP3, 0);
    mma_gemm<<<ggrid, 256, SM_TOT>>>(gP3, gA1, gX,      gP4, 1);
    proj_mma<128, 0><<<dim3(8, Bn), 256, smem0>>>(gWru, b_ru, gX, gP1, gP2, gP3, gP4,
                                                  nullptr, nullptr, gRU);

    // ---------- pass 2: candidate + output ----------
    pack2_kernel<<<packBlocks, 256>>>(inputs, hx, gRU, gX);
    mma_gemm<<<ggrid, 256, SM_TOT>>>(gX,  gA0, nullptr, gP1, 0);
    mma_gemm<<<ggrid, 256, SM_TOT>>>(gP1, gA0, gX,      gP2, 1);
    mma_gemm<<<ggrid, 256, SM_TOT>>>(gX,  gA1, nullptr, gP3, 0);
    mma_gemm<<<ggrid, 256, SM_TOT>>>(gP3, gA1, gX,      gP4, 1);
    proj_mma<64, 1><<<dim3(8, Bn), 256, smem1>>>(gWC, b_C, gX, gP1, gP2, gP3, gP4,
                                                 gRU, hx, out);
}

// round 8
// speedup vs baseline: 6.2506x; 1.8173x over previous
#include <cuda_runtime.h>
#include <cuda_fp16.h>
#include <math.h>
#include <stdint.h>

// Problem constants
#define Bn    128
#define HIDD  64
#define INDIM 2
#define CX    66
#define NN    1024
#define MROWS (Bn * CX)       // 8448

// ---------------- scratch (device globals) ----------------
__device__ __half g_X [MROWS * NN];
__device__ __half g_P1[MROWS * NN];
__device__ __half g_P2[MROWS * NN];
__device__ __half g_P3[MROWS * NN];
__device__ __half g_P4[MROWS * NN];
__device__ __half g_A [2 * NN * NN];                 // A0,A1 fp16
__device__ float  g_RU[Bn * 2 * HIDD * NN];          // sigmoid gates fp32
__device__ __half g_Wru[128 * 336];                  // W_ru fp16 (336-pad)
__device__ __half g_WC [64 * 336];                   // W_C  fp16

// ---------------- PTX helpers (base ISA only) ----------------
__device__ __forceinline__ uint32_t smem_u32(const void* p) {
    uint32_t a;
    asm("{ .reg .u64 t; cvta.to.shared.u64 t, %1; cvt.u32.u64 %0, t; }" : "=r"(a) : "l"(p));
    return a;
}
__device__ __forceinline__ void cp16(uint32_t dst, const void* src) {
    asm volatile("cp.async.cg.shared.global [%0], [%1], 16;" :: "r"(dst), "l"(src) : "memory");
}
__device__ __forceinline__ void ldm_x4(uint32_t* r, uint32_t a) {
    asm volatile("ldmatrix.sync.aligned.m8n8.x4.shared.b16 {%0,%1,%2,%3}, [%4];"
                 : "=r"(r[0]), "=r"(r[1]), "=r"(r[2]), "=r"(r[3]) : "r"(a));
}
__device__ __forceinline__ void ldm_x4t(uint32_t* r, uint32_t a) {
    asm volatile("ldmatrix.sync.aligned.m8n8.x4.trans.shared.b16 {%0,%1,%2,%3}, [%4];"
                 : "=r"(r[0]), "=r"(r[1]), "=r"(r[2]), "=r"(r[3]) : "r"(a));
}
__device__ __forceinline__ void mma16816(float* c, const uint32_t* a, const uint32_t* b) {
    asm volatile("mma.sync.aligned.m16n8k16.row.col.f32.f16.f16.f32 "
                 "{%0,%1,%2,%3},{%4,%5,%6,%7},{%8,%9},{%0,%1,%2,%3};"
                 : "+f"(c[0]), "+f"(c[1]), "+f"(c[2]), "+f"(c[3])
                 : "r"(a[0]), "r"(a[1]), "r"(a[2]), "r"(a[3]), "r"(b[0]), "r"(b[1]));
}

// ============================================================
// Big GEMM via fp16 HMMA, single term, K=1024.
// D[m,n] = X[m,:]*A[n,:];  Out = fp16( doBeta ? 2*D - X0 : D )
// CTA tile 128x128, warp tile 32x64 (8 warps), k-tile 64,
// 3-stage cp.async pipeline, 2 CTAs/SM.
// ============================================================
#define MB 128
#define NT 16
#define STG_BYTES 32768            // (128+128)*64*2
#define SM_TOT (3 * STG_BYTES)     // 98304

__global__ void __launch_bounds__(256, 2)
mma_gemm(const __half* __restrict__ Xin,
         const __half* __restrict__ Ain,
         const __half* __restrict__ X0,
         __half* __restrict__ Out,
         int doBeta)
{
    extern __shared__ char smem[];
    const uint32_t sb = smem_u32(smem);
    const int tid  = threadIdx.x;
    const int lane = tid & 31;
    const int wid  = tid >> 5;
    const int wm   = wid & 3;
    const int wn   = wid >> 2;
    const int bm   = blockIdx.y * MB;
    const int bn   = blockIdx.x * MB;

    float acc[2][8][4];
#pragma unroll
    for (int t2 = 0; t2 < 2; t2++)
#pragma unroll
        for (int j = 0; j < 8; j++)
#pragma unroll
            for (int e = 0; e < 4; e++) acc[t2][j][e] = 0.0f;

    auto fill = [&](int t) {
        const int kt = t * 64;
        const uint32_t sa = sb + (t % 3) * STG_BYTES;
        const uint32_t sB = sa + 16384;
#pragma unroll
        for (int j = 0; j < 4; j++) {
            const int u = tid + j * 256;
            const int row = u >> 3, ch = u & 7;
            cp16(sa + row * 128 + ((ch ^ (row & 7)) << 4),
                 Xin + (size_t)(bm + row) * NN + kt + ch * 8);
        }
#pragma unroll
        for (int j = 0; j < 4; j++) {
            const int u = tid + j * 256;
            const int row = u >> 3, ch = u & 7;
            cp16(sB + row * 128 + ((ch ^ (row & 7)) << 4),
                 Ain + (size_t)(bn + row) * NN + kt + ch * 8);
        }
        asm volatile("cp.async.commit_group;" ::: "memory");
    };

    const int arow_l = (lane & 15);
    const int ach_l  = (lane >> 4);
    const int bgrp   = lane >> 3;
    const int brow_l = (lane & 7) + ((bgrp >> 1) << 3);
    const int bch_l  = (bgrp & 1);

    fill(0);
    fill(1);

    for (int t = 0; t < NT; t++) {
        if (t < NT - 1) asm volatile("cp.async.wait_group 1;" ::: "memory");
        else            asm volatile("cp.async.wait_group 0;" ::: "memory");
        __syncthreads();
        if (t + 2 < NT) fill(t + 2);

        const uint32_t sa = sb + (t % 3) * STG_BYTES;
        const uint32_t sB = sa + 16384;
#pragma unroll
        for (int ks = 0; ks < 4; ks++) {
            uint32_t afr[2][4];
#pragma unroll
            for (int t2 = 0; t2 < 2; t2++) {
                const int row = wm * 32 + t2 * 16 + arow_l;
                const int ch  = 2 * ks + ach_l;
                ldm_x4(afr[t2], sa + row * 128 + ((ch ^ (row & 7)) << 4));
            }
            uint32_t bfr[4][4];
#pragma unroll
            for (int tn = 0; tn < 4; tn++) {
                const int row = wn * 64 + tn * 16 + brow_l;
                const int ch  = 2 * ks + bch_l;
                ldm_x4(bfr[tn], sB + row * 128 + ((ch ^ (row & 7)) << 4));
            }
#pragma unroll
            for (int t2 = 0; t2 < 2; t2++)
#pragma unroll
                for (int j = 0; j < 8; j++)
                    mma16816(acc[t2][j], afr[t2], &bfr[j >> 1][(j & 1) * 2]);
        }
    }

    // ---- epilogue: (optional 2*D - X0), store fp16 ----
    const int g  = lane >> 2;
    const int c2 = (lane & 3) * 2;
#pragma unroll
    for (int t2 = 0; t2 < 2; t2++) {
#pragma unroll
        for (int j = 0; j < 8; j++) {
            const int col = bn + wn * 64 + j * 8 + c2;
#pragma unroll
            for (int half = 0; half < 2; half++) {
                const int row = bm + wm * 32 + t2 * 16 + g + half * 8;
                const size_t base = (size_t)row * NN + col;
                float v0 = acc[t2][j][half * 2 + 0];
                float v1 = acc[t2][j][half * 2 + 1];
                if (doBeta) {
                    union { uint32_t u; __half h[2]; } Hh;
                    Hh.u = *(const uint32_t*)(X0 + base);
                    v0 = 2.0f * v0 - __half2float(Hh.h[0]);
                    v1 = 2.0f * v1 - __half2float(Hh.h[1]);
                }
                union { uint32_t u; __half h[2]; } Oh;
                Oh.h[0] = __float2half_rn(v0);
                Oh.h[1] = __float2half_rn(v1);
                *(uint32_t*)(Out + base) = Oh.u;
            }
        }
    }
}

// ============================================================
// Projection via fp16 HMMA, single segment, K=336 (330 + 6 pad).
// MODE 0: RU = sigmoid(W@H+b). MODE 1: out = u*hx+(1-u)*tanh(W@H+b).
// grid (8, Bn), 256 threads, 8 warps = 4(n) x 2(o).
// ============================================================
#define PKT 48
#define PNT 7
#define CSTR 132

template<int OTILE, int MODE>
__global__ void __launch_bounds__(256, 2)
proj_mma(const __half* __restrict__ Wsp, const float* __restrict__ bias,
         const __half* __restrict__ p0, const __half* __restrict__ p1,
         const __half* __restrict__ p2, const __half* __restrict__ p3,
         const __half* __restrict__ p4,
         const float* __restrict__ RU, const float* __restrict__ hx,
         float* __restrict__ outp)
{
    constexpr int HS_B = PKT * 256;            // 12288
    constexpr int WS_B = OTILE * 128;
    constexpr int STGP = HS_B + WS_B;
    constexpr int OW   = OTILE / 2;
    constexpr int NJ   = OW / 8;

    extern __shared__ char smem[];
    const uint32_t sb = smem_u32(smem);
    float* Cs = (float*)smem;

    const int tid  = threadIdx.x;
    const int lane = tid & 31;
    const int wid  = tid >> 5;
    const int wm   = wid & 3;
    const int wn   = wid >> 2;
    const int b    = blockIdx.y;
    const int bn0  = blockIdx.x * 128;

    float acc[2][NJ][4];
#pragma unroll
    for (int t2 = 0; t2 < 2; t2++)
#pragma unroll
        for (int j = 0; j < NJ; j++)
#pragma unroll
            for (int e = 0; e < 4; e++) acc[t2][j][e] = 0.0f;

    auto fill = [&](int t) {
        const int kt = t * PKT;
        const uint32_t hs = sb + (t & 1) * STGP;
        const uint32_t ws = hs + HS_B;
#pragma unroll
        for (int j = 0; j < 3; j++) {
            const int u = tid + j * 256;
            const int r = u >> 4, ch = u & 15;
            int c = kt + r;
            if (c >= 330) c = 0;                // W rows are zero there
            const int p  = c / 66;
            const int cc = c - p * 66;
            const __half* src = p0;
            if (p == 1) src = p1;
            else if (p == 2) src = p2;
            else if (p == 3) src = p3;
            else if (p == 4) src = p4;
            cp16(hs + r * 256 + ((ch ^ (r & 15)) << 4),
                 src + ((size_t)b * CX + cc) * NN + bn0 + ch * 8);
        }
#pragma unroll
        for (int j = 0; j < (OTILE * 6 + 255) / 256; j++) {
            const int u = tid + j * 256;
            if (u < OTILE * 6) {
                const int orow = u / 6, wc = u - orow * 6;
                cp16(ws + orow * 128 + ((wc ^ (orow & 7)) << 4),
                     Wsp + (size_t)orow * 336 + kt + wc * 8);
            }
        }
        asm volatile("cp.async.commit_group;" ::: "memory");
    };

    const int krow_l = (lane & 7) + ((lane >> 4) << 3);
    const int m8sel  = (lane >> 3) & 1;
    const int bgrp   = lane >> 3;
    const int brow_l = (lane & 7) + ((bgrp >> 1) << 3);
    const int bch_l  = (bgrp & 1);

    fill(0);
    for (int t = 0; t < PNT; t++) {
        if (t + 1 < PNT) {
            fill(t + 1);
            asm volatile("cp.async.wait_group 1;" ::: "memory");
        } else {
            asm volatile("cp.async.wait_group 0;" ::: "memory");
        }
        __syncthreads();

        const uint32_t hs = sb + (t & 1) * STGP;
        const uint32_t ws = hs + HS_B;
#pragma unroll
        for (int ks = 0; ks < 3; ks++) {
            uint32_t afr[2][4];
#pragma unroll
            for (int t2 = 0; t2 < 2; t2++) {
                const int kr  = ks * 16 + krow_l;
                const int chm = (wm * 4) + (t2 * 2) + m8sel;
                ldm_x4t(afr[t2], hs + kr * 256 + ((chm ^ (kr & 15)) << 4));
            }
            uint32_t bfr[NJ / 2 > 0 ? NJ / 2 : 1][4];
#pragma unroll
            for (int tn = 0; tn < NJ / 2; tn++) {
                const int row = wn * OW + tn * 16 + brow_l;
                const int ch  = 2 * ks + bch_l;
                ldm_x4(bfr[tn], ws + row * 128 + ((ch ^ (row & 7)) << 4));
            }
#pragma unroll
            for (int t2 = 0; t2 < 2; t2++)
#pragma unroll
                for (int j = 0; j < NJ; j++)
                    mma16816(acc[t2][j], afr[t2], &bfr[j >> 1][(j & 1) * 2]);
        }
        __syncthreads();
    }

    __syncthreads();
    const int g  = lane >> 2;
    const int c2 = (lane & 3) * 2;
#pragma unroll
    for (int t2 = 0; t2 < 2; t2++)
#pragma unroll
        for (int j = 0; j < NJ; j++)
#pragma unroll
            for (int e = 0; e < 4; e++) {
                const int n = wm * 32 + t2 * 16 + g + (e >> 1) * 8;
                const int o = wn * OW + j * 8 + c2 + (e & 1);
                Cs[o * CSTR + n] = acc[t2][j][e];
            }
    __syncthreads();

    for (int o = wid; o < OTILE; o += 8) {
        const float bv = bias[o];
        const int n = lane * 4;
        float4 v = *(float4*)&Cs[o * CSTR + n];
        if (MODE == 0) {
            v.x = 1.0f / (1.0f + expf(-(v.x + bv)));
            v.y = 1.0f / (1.0f + expf(-(v.y + bv)));
            v.z = 1.0f / (1.0f + expf(-(v.z + bv)));
            v.w = 1.0f / (1.0f + expf(-(v.w + bv)));
            *(float4*)(outp + ((size_t)b * 128 + o) * NN + bn0 + n) = v;
        } else {
            const float4 u4 = *(const float4*)(RU + ((size_t)b * 128 + 64 + o) * NN + bn0 + n);
            const float4 h4 = *(const float4*)(hx + ((size_t)b * HIDD + o) * NN + bn0 + n);
            float4 r;
            r.x = u4.x * h4.x + (1.0f - u4.x) * tanhf(v.x + bv);
            r.y = u4.y * h4.y + (1.0f - u4.y) * tanhf(v.y + bv);
            r.z = u4.z * h4.z + (1.0f - u4.z) * tanhf(v.z + bv);
            r.w = u4.w * h4.w + (1.0f - u4.w) * tanhf(v.w + bv);
            *(float4*)(outp + ((size_t)b * HIDD + o) * NN + bn0 + n) = r;
        }
    }
}

// ============================================================
// pack / convert kernels (fp32 -> single fp16)
// ============================================================
__global__ void splitA_kernel(const float* __restrict__ A0, const float* __restrict__ A1,
                              __half* __restrict__ Aout)
{
    const int idx = blockIdx.x * blockDim.x + threadIdx.x;   // 2*1024*256
    if (idx >= 2 * NN * 256) return;
    const int adj = idx >> 18;
    const int r   = idx & ((1 << 18) - 1);
    const int row = r >> 8;
    const int n4  = r & 255;
    const float4 v = ((const float4*)(adj ? A1 : A0))[(size_t)row * 256 + n4];
    union { uint2 u; __half h[4]; } H;
    H.h[0] = __float2half_rn(v.x);
    H.h[1] = __float2half_rn(v.y);
    H.h[2] = __float2half_rn(v.z);
    H.h[3] = __float2half_rn(v.w);
    *(uint2*)(Aout + (size_t)(adj * NN + row) * NN + n4 * 4) = H.u;
}

__global__ void splitW_kernel(const float* __restrict__ W_ru, const float* __restrict__ W_C,
                              __half* __restrict__ Wru, __half* __restrict__ WC)
{
    const int idx = blockIdx.x * blockDim.x + threadIdx.x;
    if (idx >= 192 * 336) return;
    const int o = idx / 336;
    const int c = idx - o * 336;
    float w = 0.0f;
    if (c < 330) w = (o < 128) ? W_ru[(size_t)o * 330 + c] : W_C[(size_t)(o - 128) * 330 + c];
    const __half h = __float2half_rn(w);
    if (o < 128) Wru[(size_t)o * 336 + c] = h;
    else         WC[(size_t)(o - 128) * 336 + c] = h;
}

__global__ void pack1_kernel(const float* __restrict__ inputs, const float* __restrict__ hx,
                             __half* __restrict__ X)
{
    const int idx = blockIdx.x * blockDim.x + threadIdx.x;
    if (idx >= MROWS * 256) return;
    const int n4 = idx & 255;
    const int t  = idx >> 8;
    const int c  = t % CX;
    const int b  = t / CX;
    float4 v;
    if (c < INDIM)
        v = ((const float4*)inputs)[((size_t)b * INDIM + c) * 256 + n4];
    else
        v = ((const float4*)hx)[((size_t)b * HIDD + (c - INDIM)) * 256 + n4];
    union { uint2 u; __half h[4]; } H;
    H.h[0] = __float2half_rn(v.x);
    H.h[1] = __float2half_rn(v.y);
    H.h[2] = __float2half_rn(v.z);
    H.h[3] = __float2half_rn(v.w);
    *(uint2*)(X + (size_t)t * NN + n4 * 4) = H.u;
}

__global__ void pack2_kernel(const float* __restrict__ inputs, const float* __restrict__ hx,
                             const float* __restrict__ RU, __half* __restrict__ X)
{
    const int idx = blockIdx.x * blockDim.x + threadIdx.x;
    if (idx >= MROWS * 256) return;
    const int n4 = idx & 255;
    const int t  = idx >> 8;
    const int c  = t % CX;
    const int b  = t / CX;
    float4 v;
    if (c < INDIM) {
        v = ((const float4*)inputs)[((size_t)b * INDIM + c) * 256 + n4];
    } else {
        const int cc = c - INDIM;
        const float4 r = ((const float4*)RU)[((size_t)b * 128 + cc) * 256 + n4];
        const float4 h = ((const float4*)hx)[((size_t)b * HIDD + cc) * 256 + n4];
        v.x = r.x * h.x; v.y = r.y * h.y; v.z = r.z * h.z; v.w = r.w * h.w;
    }
    union { uint2 u; __half h[4]; } H;
    H.h[0] = __float2half_rn(v.x);
    H.h[1] = __float2half_rn(v.y);
    H.h[2] = __float2half_rn(v.z);
    H.h[3] = __float2half_rn(v.w);
    *(uint2*)(X + (size_t)t * NN + n4 * 4) = H.u;
}

// ============================================================
extern "C" void kernel_launch(void* const* d_in, const int* in_sizes, int n_in,
                              void* d_out, int out_size)
{
    const float* inputs = (const float*)d_in[0];
    const float* hx     = (const float*)d_in[1];
    const float* A0     = (const float*)d_in[2];
    const float* A1     = (const float*)d_in[3];
    const float* W_ru   = (const float*)d_in[4];
    const float* b_ru   = (const float*)d_in[5];
    const float* W_C    = (const float*)d_in[6];
    const float* b_C    = (const float*)d_in[7];
    float* out = (float*)d_out;

    __half *gX, *gP1, *gP2, *gP3, *gP4, *gA, *gWru, *gWC;
    float *gRU;
    cudaGetSymbolAddress((void**)&gX,  g_X);
    cudaGetSymbolAddress((void**)&gP1, g_P1);
    cudaGetSymbolAddress((void**)&gP2, g_P2);
    cudaGetSymbolAddress((void**)&gP3, g_P3);
    cudaGetSymbolAddress((void**)&gP4, g_P4);
    cudaGetSymbolAddress((void**)&gA,  g_A);
    cudaGetSymbolAddress((void**)&gRU, g_RU);
    cudaGetSymbolAddress((void**)&gWru, g_Wru);
    cudaGetSymbolAddress((void**)&gWC,  g_WC);

    static bool attr_set = false;
    if (!attr_set) {
        cudaFuncSetAttribute(mma_gemm, cudaFuncAttributeMaxDynamicSharedMemorySize, SM_TOT);
        cudaFuncSetAttribute(proj_mma<128, 0>, cudaFuncAttributeMaxDynamicSharedMemorySize, 128 * CSTR * 4);
        cudaFuncSetAttribute(proj_mma<64, 1>,  cudaFuncAttributeMaxDynamicSharedMemorySize, 64 * 1024);
        attr_set = true;
    }
    const int smem0 = 128 * CSTR * 4;                         // 67584 >= pipe 57344
    const int pipe1 = 2 * (PKT * 256 + 64 * 128);             // 40960
    const int cs1   = 64 * CSTR * 4;                          // 33792
    const int smem1 = pipe1 > cs1 ? pipe1 : cs1;

    const dim3 ggrid(NN / MB, MROWS / MB);   // (8, 66)
    const int packBlocks = (MROWS * 256 + 255) / 256;
    const __half* gA0 = gA;
    const __half* gA1 = gA + (size_t)NN * NN;

    splitA_kernel<<<(2 * NN * 256 + 255) / 256, 256>>>(A0, A1, gA);
    splitW_kernel<<<(192 * 336 + 255) / 256, 256>>>(W_ru, W_C, gWru, gWC);

    // ---------- pass 1: ru gates ----------
    pack1_kernel<<<packBlocks, 256>>>(inputs, hx, gX);
    mma_gemm<<<ggrid, 256, SM_TOT>>>(gX,  gA0, nullptr, gP1, 0);
    mma_gemm<<<ggrid, 256, SM_TOT>>>(gP1, gA0, gX,      gP2, 1);
    mma_gemm<<<ggrid, 256, SM_TOT>>>(gX,  gA1, nullptr, gP3, 0);
    mma_gemm<<<ggrid, 256, SM_TOT>>>(gP3, gA1, gX,      gP4, 1);
    proj_mma<128, 0><<<dim3(8, Bn), 256, smem0>>>(gWru, b_ru, gX, gP1, gP2, gP3, gP4,
                                                  nullptr, nullptr, gRU);

    // ---------- pass 2: candidate + output ----------
    pack2_kernel<<<packBlocks, 256>>>(inputs, hx, gRU, gX);
    mma_gemm<<<ggrid, 256, SM_TOT>>>(gX,  gA0, nullptr, gP1, 0);
    mma_gemm<<<ggrid, 256, SM_TOT>>>(gP1, gA0, gX,      gP2, 1);
    mma_gemm<<<ggrid, 256, SM_TOT>>>(gX,  gA1, nullptr, gP3, 0);
    mma_gemm<<<ggrid, 256, SM_TOT>>>(gP3, gA1, gX,      gP4, 1);
    proj_mma<64, 1><<<dim3(8, Bn), 256, smem1>>>(gWC, b_C, gX, gP1, gP2, gP3, gP4,
                                                 gRU, hx, out);
}